// round 5
// baseline (speedup 1.0000x reference)
#include <cuda_runtime.h>
#include <cuda_bf16.h>
#include <float.h>
#include <stdint.h>

#define D_DIM   64
#define K_CODES 512
#define BLOCK   128
#define GRID    148
#define NROWS   65536
#define NTILES  512

// ---- SMEM layout (bytes). B splits stored [n][k], row stride 72 halves (144B):
// bank = (4n + 8ks + c) mod 32 -> conflict-free B-fragment loads.
#define SM_EH 0
#define SM_EM 73728
#define SM_EL 147456
#define SM_SN 221184            // 512 floats
#define SM_BK 223232            // 128 ints
#define SM_LS 223744            // 4 doubles
#define SMEM_TOTAL 223808

__device__ float        g_embT[K_CODES * D_DIM];   // exact fp32 codebook, [k][d]
__device__ double       g_partial[GRID];
__device__ unsigned int g_cnt = 0;

#define MMA(acc, a, b0, b1)                                                     \
    asm volatile(                                                               \
        "mma.sync.aligned.m16n8k16.row.col.f32.bf16.bf16.f32 "                  \
        "{%0,%1,%2,%3}, {%4,%5,%6,%7}, {%8,%9}, {%0,%1,%2,%3};"                 \
        : "+f"(acc[0]), "+f"(acc[1]), "+f"(acc[2]), "+f"(acc[3])                \
        : "r"((a)[0]), "r"((a)[1]), "r"((a)[2]), "r"((a)[3]), "r"(b0), "r"(b1))

__device__ __forceinline__ uint32_t pack_bf2(__nv_bfloat16 lo, __nv_bfloat16 hi) {
    return (uint32_t)__bfloat16_as_ushort(lo) | ((uint32_t)__bfloat16_as_ushort(hi) << 16);
}

// 3-way exact-residual bf16 split of a float pair (a = lower k-col, b = upper)
__device__ __forceinline__ void split3(float a, float b,
                                       uint32_t& ph, uint32_t& pm, uint32_t& pl) {
    __nv_bfloat16 ha = __float2bfloat16(a), hb = __float2bfloat16(b);
    float ra = a - __bfloat162float(ha), rb = b - __bfloat162float(hb);
    __nv_bfloat16 ma = __float2bfloat16(ra), mb = __float2bfloat16(rb);
    float r2a = ra - __bfloat162float(ma), r2b = rb - __bfloat162float(mb);
    __nv_bfloat16 la = __float2bfloat16(r2a), lb = __float2bfloat16(r2b);
    ph = pack_bf2(ha, hb); pm = pack_bf2(ma, mb); pl = pack_bf2(la, lb);
}

__device__ __forceinline__ void upd(float& b, int& bi, float d, int idx) {
    if (d < b) { b = d; bi = idx; }
}

__global__ void __launch_bounds__(BLOCK, 1)
vq_mma(const float* __restrict__ x, const float* __restrict__ emb,
       float* __restrict__ out, int write_loss)
{
    extern __shared__ char smem[];
    uint16_t* sEH = (uint16_t*)(smem + SM_EH);
    uint16_t* sEM = (uint16_t*)(smem + SM_EM);
    uint16_t* sEL = (uint16_t*)(smem + SM_EL);
    float*    snm = (float*)(smem + SM_SN);
    int*      sbk = (int*)(smem + SM_BK);
    double*   sls = (double*)(smem + SM_LS);

    const int tid  = threadIdx.x;
    const int w    = tid >> 5;
    const int lane = tid & 31;
    const int g    = lane >> 2;   // group (row within m-tile half)
    const int c    = lane & 3;    // thread-in-group (col pair selector)

    // ---- Prologue: codebook splits -> SMEM; exact fp32 transpose -> global ----
    for (int i = tid; i < K_CODES * D_DIM; i += BLOCK) {
        int d = i >> 9;             // emb layout [d][k]
        int k = i & (K_CODES - 1);
        float v = emb[i];
        uint32_t ph, pm, pl;        // pack scalar with 0 partner, store halves
        __nv_bfloat16 h = __float2bfloat16(v);
        float r = v - __bfloat162float(h);
        __nv_bfloat16 m = __float2bfloat16(r);
        float r2 = r - __bfloat162float(m);
        __nv_bfloat16 l = __float2bfloat16(r2);
        (void)ph; (void)pm; (void)pl;
        sEH[k * 72 + d] = __bfloat16_as_ushort(h);
        sEM[k * 72 + d] = __bfloat16_as_ushort(m);
        sEL[k * 72 + d] = __bfloat16_as_ushort(l);
        g_embT[k * 64 + d] = v;
    }
    for (int k = tid; k < K_CODES; k += BLOCK) {
        float s = 0.f;
        #pragma unroll 8
        for (int d = 0; d < D_DIM; d++) { float v = emb[d * K_CODES + k]; s = fmaf(v, v, s); }
        snm[k] = s;
    }
    __syncthreads();

    const uint32_t* EH = (const uint32_t*)sEH;
    const uint32_t* EM = (const uint32_t*)sEM;
    const uint32_t* EL = (const uint32_t*)sEL;

    double lacc = 0.0;

    for (int tile = blockIdx.x; tile < NTILES; tile += GRID) {
        const int rbase = tile * BLOCK + w * 32 + g;

        // ---- A fragments from global x (each element read once per CTA) ----
        uint32_t Ah[2][4][4], Am[2][4][4], Al[2][4][4];  // [mtile][kstep][reg]
        float xn0 = 0.f, xn1 = 0.f, xn2 = 0.f, xn3 = 0.f;
        #pragma unroll
        for (int mt = 0; mt < 2; mt++) {
            const float* xr0 = x + (size_t)(rbase + mt * 16) * D_DIM;
            const float* xr1 = xr0 + 8 * D_DIM;
            #pragma unroll
            for (int ks = 0; ks < 4; ks++) {
                #pragma unroll
                for (int p = 0; p < 2; p++) {
                    int col = 2 * c + 8 * p + 16 * ks;
                    float2 v0 = *(const float2*)(xr0 + col);
                    float2 v1 = *(const float2*)(xr1 + col);
                    float s0 = fmaf(v0.x, v0.x, v0.y * v0.y);
                    float s1 = fmaf(v1.x, v1.x, v1.y * v1.y);
                    if (mt == 0) { xn0 += s0; xn1 += s1; } else { xn2 += s0; xn3 += s1; }
                    split3(v0.x, v0.y, Ah[mt][ks][2*p],   Am[mt][ks][2*p],   Al[mt][ks][2*p]);
                    split3(v1.x, v1.y, Ah[mt][ks][2*p+1], Am[mt][ks][2*p+1], Al[mt][ks][2*p+1]);
                }
            }
        }

        float best0 = FLT_MAX, best1 = FLT_MAX, best2 = FLT_MAX, best3 = FLT_MAX;
        int   bi0 = 0, bi1 = 0, bi2 = 0, bi3 = 0;

        // ---- main loop over 64 n-tiles, 2 at a time ----
        for (int nt = 0; nt < 64; nt += 2) {
            float acc[2][2][4];
            #pragma unroll
            for (int u = 0; u < 2; u++)
                #pragma unroll
                for (int m2 = 0; m2 < 2; m2++)
                    #pragma unroll
                    for (int r2 = 0; r2 < 4; r2++) acc[u][m2][r2] = 0.f;

            #pragma unroll
            for (int ks = 0; ks < 4; ks++) {
                #pragma unroll
                for (int u = 0; u < 2; u++) {
                    const int widx = (8 * (nt + u) + g) * 36 + 8 * ks + c;
                    uint32_t bh0 = EH[widx], bh1 = EH[widx + 4];
                    MMA(acc[u][0], Ah[0][ks], bh0, bh1);
                    MMA(acc[u][1], Ah[1][ks], bh0, bh1);
                    MMA(acc[u][0], Am[0][ks], bh0, bh1);
                    MMA(acc[u][1], Am[1][ks], bh0, bh1);
                    MMA(acc[u][0], Al[0][ks], bh0, bh1);
                    MMA(acc[u][1], Al[1][ks], bh0, bh1);
                    uint32_t bm0 = EM[widx], bm1 = EM[widx + 4];
                    MMA(acc[u][0], Ah[0][ks], bm0, bm1);
                    MMA(acc[u][1], Ah[1][ks], bm0, bm1);
                    MMA(acc[u][0], Am[0][ks], bm0, bm1);
                    MMA(acc[u][1], Am[1][ks], bm0, bm1);
                    uint32_t bl0 = EL[widx], bl1 = EL[widx + 4];
                    MMA(acc[u][0], Ah[0][ks], bl0, bl1);
                    MMA(acc[u][1], Ah[1][ks], bl0, bl1);
                }
            }

            #pragma unroll
            for (int u = 0; u < 2; u++) {
                const int base = 8 * (nt + u) + 2 * c;
                float2 s2 = *(const float2*)(snm + base);
                upd(best0, bi0, fmaf(-2.f, acc[u][0][0], s2.x), base);
                upd(best0, bi0, fmaf(-2.f, acc[u][0][1], s2.y), base + 1);
                upd(best1, bi1, fmaf(-2.f, acc[u][0][2], s2.x), base);
                upd(best1, bi1, fmaf(-2.f, acc[u][0][3], s2.y), base + 1);
                upd(best2, bi2, fmaf(-2.f, acc[u][1][0], s2.x), base);
                upd(best2, bi2, fmaf(-2.f, acc[u][1][1], s2.y), base + 1);
                upd(best3, bi3, fmaf(-2.f, acc[u][1][2], s2.x), base);
                upd(best3, bi3, fmaf(-2.f, acc[u][1][3], s2.y), base + 1);
            }
        }

        // ---- quad reduce (lanes xor 1,2 share the same rows) ----
        #pragma unroll
        for (int off = 1; off <= 2; off <<= 1) {
            float ob; int oi; float ox;
            ob = __shfl_xor_sync(0xffffffffu, best0, off);
            oi = __shfl_xor_sync(0xffffffffu, bi0,   off);
            if (ob < best0 || (ob == best0 && oi < bi0)) { best0 = ob; bi0 = oi; }
            ob = __shfl_xor_sync(0xffffffffu, best1, off);
            oi = __shfl_xor_sync(0xffffffffu, bi1,   off);
            if (ob < best1 || (ob == best1 && oi < bi1)) { best1 = ob; bi1 = oi; }
            ob = __shfl_xor_sync(0xffffffffu, best2, off);
            oi = __shfl_xor_sync(0xffffffffu, bi2,   off);
            if (ob < best2 || (ob == best2 && oi < bi2)) { best2 = ob; bi2 = oi; }
            ob = __shfl_xor_sync(0xffffffffu, best3, off);
            oi = __shfl_xor_sync(0xffffffffu, bi3,   off);
            if (ob < best3 || (ob == best3 && oi < bi3)) { best3 = ob; bi3 = oi; }
            ox = __shfl_xor_sync(0xffffffffu, xn0, off); xn0 += ox;
            ox = __shfl_xor_sync(0xffffffffu, xn1, off); xn1 += ox;
            ox = __shfl_xor_sync(0xffffffffu, xn2, off); xn2 += ox;
            ox = __shfl_xor_sync(0xffffffffu, xn3, off); xn3 += ox;
        }

        if (c == 0) {
            const int r = w * 32 + g;
            sbk[r]      = bi0;
            sbk[r + 8]  = bi1;
            sbk[r + 16] = bi2;
            sbk[r + 24] = bi3;
            lacc += (double)(xn0 + best0) + (double)(xn1 + best1)
                  + (double)(xn2 + best2) + (double)(xn3 + best3);
        }
        __syncthreads();

        // ---- output: exact fp32 codebook row ----
        {
            const int k = sbk[tid];
            const float4* src = (const float4*)(g_embT + k * D_DIM);
            float4* dst = (float4*)(out + (size_t)(tile * BLOCK + tid) * D_DIM);
            #pragma unroll
            for (int j = 0; j < 16; j++) dst[j] = src[j];
        }
        __syncthreads();   // sbk reused next tile
    }

    // ---- loss: warp reduce -> CTA -> per-CTA partial -> last block finalizes ----
    #pragma unroll
    for (int off = 16; off > 0; off >>= 1)
        lacc += __shfl_down_sync(0xffffffffu, lacc, off);
    if (lane == 0) sls[w] = lacc;
    __syncthreads();
    if (tid == 0) {
        g_partial[blockIdx.x] = sls[0] + sls[1] + sls[2] + sls[3];
        __threadfence();
        unsigned t = atomicAdd(&g_cnt, 1u);
        if (t == GRID - 1) {
            __threadfence();
            double tot = 0.0;
            for (int i = 0; i < GRID; i++) tot += g_partial[i];
            if (write_loss)
                out[(size_t)NROWS * D_DIM] =
                    (float)(tot * (1.25 / ((double)NROWS * (double)D_DIM)));
            g_cnt = 0;   // reset for next graph replay
        }
    }
}

extern "C" void kernel_launch(void* const* d_in, const int* in_sizes, int n_in,
                              void* d_out, int out_size)
{
    const float* x   = (const float*)d_in[0];   // (64,32,32,64) fp32
    const float* emb = (const float*)d_in[1];   // (64,512) fp32
    float* out = (float*)d_out;

    const int write_loss = (out_size > NROWS * D_DIM) ? 1 : 0;

    static int configured = 0;
    if (!configured) {
        cudaFuncSetAttribute(vq_mma, cudaFuncAttributeMaxDynamicSharedMemorySize, SMEM_TOTAL);
        configured = 1;
    }
    vq_mma<<<GRID, BLOCK, SMEM_TOTAL>>>(x, emb, out, write_loss);
}

// round 6
// speedup vs baseline: 1.8382x; 1.8382x over previous
#include <cuda_runtime.h>
#include <cuda_bf16.h>
#include <float.h>
#include <stdint.h>

#define D_DIM   64
#define K_CODES 512
#define BLOCK   256          // 8 warps
#define GRID    148
#define NROWS   65536
#define NTILES  512          // 128 rows per tile

// ---- SMEM layout (bytes) ----
// B fragments in mma-fragment order, idx = ((nt*4+ks)*32 + lane):
//   sHM: uint4 {bh0, bh1, bm0, bm1}   (8192 * 16B = 128KB)
//   sL : uint2 {bl0, bl1}             (8192 *  8B =  64KB)
#define SM_HM 0
#define SM_L  131072
#define SM_SN 196608         // 512 floats
#define SM_BK 198656         // 128 ints
#define SM_LS 199168         // 8 doubles
#define SMEM_TOTAL 199232

__device__ float        g_embT[K_CODES * D_DIM];   // exact fp32 codebook [k][d]
__device__ double       g_partial[GRID];
__device__ unsigned int g_cnt = 0;

#define MMA(acc, a, b0, b1)                                                     \
    asm volatile(                                                               \
        "mma.sync.aligned.m16n8k16.row.col.f32.bf16.bf16.f32 "                  \
        "{%0,%1,%2,%3}, {%4,%5,%6,%7}, {%8,%9}, {%0,%1,%2,%3};"                 \
        : "+f"((acc)[0]), "+f"((acc)[1]), "+f"((acc)[2]), "+f"((acc)[3])        \
        : "r"((a)[0]), "r"((a)[1]), "r"((a)[2]), "r"((a)[3]), "r"(b0), "r"(b1))

__device__ __forceinline__ uint32_t pack_bf2(__nv_bfloat16 lo, __nv_bfloat16 hi) {
    return (uint32_t)__bfloat16_as_ushort(lo) | ((uint32_t)__bfloat16_as_ushort(hi) << 16);
}

// 3-way exact-residual bf16 split of a float pair
__device__ __forceinline__ void split3(float a, float b,
                                       uint32_t& ph, uint32_t& pm, uint32_t& pl) {
    __nv_bfloat16 ha = __float2bfloat16(a), hb = __float2bfloat16(b);
    float ra = a - __bfloat162float(ha), rb = b - __bfloat162float(hb);
    __nv_bfloat16 ma = __float2bfloat16(ra), mb = __float2bfloat16(rb);
    float r2a = ra - __bfloat162float(ma), r2b = rb - __bfloat162float(mb);
    __nv_bfloat16 la = __float2bfloat16(r2a), lb = __float2bfloat16(r2b);
    ph = pack_bf2(ha, hb); pm = pack_bf2(ma, mb); pl = pack_bf2(la, lb);
}

__device__ __forceinline__ void upd(float& b, int& bi, float d, int idx) {
    if (d < b) { b = d; bi = idx; }
}

__global__ void __launch_bounds__(BLOCK, 1)
vq_mma(const float* __restrict__ x, const float* __restrict__ emb,
       float* __restrict__ out, int write_loss)
{
    extern __shared__ char smem[];
    uint4*  sHM = (uint4*)(smem + SM_HM);
    uint2*  sL  = (uint2*)(smem + SM_L);
    float*  snm = (float*)(smem + SM_SN);
    int*    sbk = (int*)(smem + SM_BK);
    double* sls = (double*)(smem + SM_LS);

    const int tid  = threadIdx.x;
    const int w    = tid >> 5;
    const int lane = tid & 31;
    const int g    = lane >> 2;
    const int c    = lane & 3;

    // ---- Prologue: build B fragments (3-way bf16 split) + exact fp32 transpose ----
    for (int i = tid; i < 8192; i += BLOCK) {
        int nt = i >> 7;
        int ks = (i >> 5) & 3;
        int ln = i & 31;
        int fg = ln >> 2, fc = ln & 3;
        int n  = nt * 8 + fg;
        int d0 = ks * 16 + fc * 2;
        // b0 covers k = d0, d0+1 ; b1 covers k = d0+8, d0+9
        float e00 = __ldg(emb + (d0 + 0) * K_CODES + n);
        float e01 = __ldg(emb + (d0 + 1) * K_CODES + n);
        float e10 = __ldg(emb + (d0 + 8) * K_CODES + n);
        float e11 = __ldg(emb + (d0 + 9) * K_CODES + n);
        uint32_t bh0, bm0, bl0, bh1, bm1, bl1;
        split3(e00, e01, bh0, bm0, bl0);
        split3(e10, e11, bh1, bm1, bl1);
        sHM[i] = make_uint4(bh0, bh1, bm0, bm1);
        sL[i]  = make_uint2(bl0, bl1);
        g_embT[n * D_DIM + d0]     = e00;
        g_embT[n * D_DIM + d0 + 1] = e01;
        g_embT[n * D_DIM + d0 + 8] = e10;
        g_embT[n * D_DIM + d0 + 9] = e11;
    }
    for (int k = tid; k < K_CODES; k += BLOCK) {
        float s = 0.f;
        #pragma unroll 8
        for (int d = 0; d < D_DIM; d++) { float v = emb[d * K_CODES + k]; s = fmaf(v, v, s); }
        snm[k] = s;
    }
    __syncthreads();

    double lacc = 0.0;

    for (int tile = blockIdx.x; tile < NTILES; tile += GRID) {
        const int rbase = tile * BLOCK / 2 + w * 16 + g;   // tile covers 128 rows

        // ---- A fragments: rows rbase (g) and rbase+8, 3 splits, 4 k-steps ----
        uint32_t Ah[4][4], Am[4][4], Al[4][4];
        float xn0 = 0.f, xn1 = 0.f;
        {
            const float* xr0 = x + (size_t)rbase * D_DIM;
            const float* xr1 = xr0 + 8 * D_DIM;
            #pragma unroll
            for (int ks = 0; ks < 4; ks++) {
                #pragma unroll
                for (int p = 0; p < 2; p++) {
                    int col = 2 * c + 8 * p + 16 * ks;
                    float2 v0 = *(const float2*)(xr0 + col);
                    float2 v1 = *(const float2*)(xr1 + col);
                    xn0 = fmaf(v0.x, v0.x, fmaf(v0.y, v0.y, xn0));
                    xn1 = fmaf(v1.x, v1.x, fmaf(v1.y, v1.y, xn1));
                    split3(v0.x, v0.y, Ah[ks][2*p],   Am[ks][2*p],   Al[ks][2*p]);
                    split3(v1.x, v1.y, Ah[ks][2*p+1], Am[ks][2*p+1], Al[ks][2*p+1]);
                }
            }
        }

        float best0 = FLT_MAX, best1 = FLT_MAX;
        int   bi0 = 0, bi1 = 0;

        // ---- main loop: 64 n-tiles, 4 at a time (4 independent acc chains) ----
        #pragma unroll 1
        for (int nt0 = 0; nt0 < 64; nt0 += 4) {
            float acc[4][4];
            #pragma unroll
            for (int u = 0; u < 4; u++)
                #pragma unroll
                for (int r = 0; r < 4; r++) acc[u][r] = 0.f;

            #pragma unroll
            for (int ks = 0; ks < 4; ks++) {
                #pragma unroll
                for (int u = 0; u < 4; u++) {
                    const int idx = ((nt0 + u) * 4 + ks) * 32 + lane;
                    uint4 hm = sHM[idx];      // {bh0, bh1, bm0, bm1}
                    uint2 lo = sL[idx];       // {bl0, bl1}
                    MMA(acc[u], Ah[ks], hm.x, hm.y);   // hh
                    MMA(acc[u], Am[ks], hm.x, hm.y);   // mh
                    MMA(acc[u], Al[ks], hm.x, hm.y);   // lh
                    MMA(acc[u], Ah[ks], hm.z, hm.w);   // hm
                    MMA(acc[u], Am[ks], hm.z, hm.w);   // mm
                    MMA(acc[u], Ah[ks], lo.x, lo.y);   // hl
                }
            }

            #pragma unroll
            for (int u = 0; u < 4; u++) {
                const int kb = (nt0 + u) * 8 + 2 * c;
                float2 s2 = *(const float2*)(snm + kb);
                upd(best0, bi0, fmaf(-2.f, acc[u][0], s2.x), kb);
                upd(best0, bi0, fmaf(-2.f, acc[u][1], s2.y), kb + 1);
                upd(best1, bi1, fmaf(-2.f, acc[u][2], s2.x), kb);
                upd(best1, bi1, fmaf(-2.f, acc[u][3], s2.y), kb + 1);
            }
        }

        // ---- quad reduce across c (lanes xor 1,2 share rows) ----
        #pragma unroll
        for (int off = 1; off <= 2; off <<= 1) {
            float ob; int oi; float ox;
            ob = __shfl_xor_sync(0xffffffffu, best0, off);
            oi = __shfl_xor_sync(0xffffffffu, bi0,   off);
            if (ob < best0 || (ob == best0 && oi < bi0)) { best0 = ob; bi0 = oi; }
            ob = __shfl_xor_sync(0xffffffffu, best1, off);
            oi = __shfl_xor_sync(0xffffffffu, bi1,   off);
            if (ob < best1 || (ob == best1 && oi < bi1)) { best1 = ob; bi1 = oi; }
            ox = __shfl_xor_sync(0xffffffffu, xn0, off); xn0 += ox;
            ox = __shfl_xor_sync(0xffffffffu, xn1, off); xn1 += ox;
        }

        if (c == 0) {
            sbk[w * 16 + g]     = bi0;
            sbk[w * 16 + g + 8] = bi1;
            lacc += (double)(xn0 + best0) + (double)(xn1 + best1);
        }
        __syncthreads();

        // ---- output: exact fp32 codebook rows (2 threads per row) ----
        {
            const int r    = tid >> 1;          // 0..127
            const int half = tid & 1;
            const int k    = sbk[r];
            const float4* src = (const float4*)(g_embT + k * D_DIM) + half * 8;
            float4* dst = (float4*)(out + (size_t)(tile * 128 + r) * D_DIM) + half * 8;
            #pragma unroll
            for (int j = 0; j < 8; j++) dst[j] = src[j];
        }
        __syncthreads();   // sbk reused next tile
    }

    // ---- loss: warp reduce -> CTA partial -> last block finalizes ----
    #pragma unroll
    for (int off = 16; off > 0; off >>= 1)
        lacc += __shfl_down_sync(0xffffffffu, lacc, off);
    if (lane == 0) sls[w] = lacc;
    __syncthreads();
    if (tid == 0) {
        double t = 0.0;
        #pragma unroll
        for (int i = 0; i < 8; i++) t += sls[i];
        g_partial[blockIdx.x] = t;
        __threadfence();
        unsigned n = atomicAdd(&g_cnt, 1u);
        if (n == GRID - 1) {
            __threadfence();
            double tot = 0.0;
            for (int i = 0; i < GRID; i++) tot += g_partial[i];
            if (write_loss)
                out[(size_t)NROWS * D_DIM] =
                    (float)(tot * (1.25 / ((double)NROWS * (double)D_DIM)));
            g_cnt = 0;   // reset for next graph replay
        }
    }
}

extern "C" void kernel_launch(void* const* d_in, const int* in_sizes, int n_in,
                              void* d_out, int out_size)
{
    const float* x   = (const float*)d_in[0];
    const float* emb = (const float*)d_in[1];
    float* out = (float*)d_out;

    const int write_loss = (out_size > NROWS * D_DIM) ? 1 : 0;

    static int configured = 0;
    if (!configured) {
        cudaFuncSetAttribute(vq_mma, cudaFuncAttributeMaxDynamicSharedMemorySize, SMEM_TOTAL);
        configured = 1;
    }
    vq_mma<<<GRID, BLOCK, SMEM_TOTAL>>>(x, emb, out, write_loss);
}